// round 14
// baseline (speedup 1.0000x reference)
#include <cuda_runtime.h>

// Segment-sum over sorted ray_indices + gather back.
// Output: d_out[0 .. n_rays*8)                    = per-ray sums
//         d_out[n_rays*8 .. n_rays*8+n_samples*8) = per-sample gathered sums
//
// Sorted indices => each ray is a contiguous pack.
//   1) boundary_kernel: streaming pass over idx -> pack offsets (static
//      __device__ scratch). Common path = predicated store (inline asm, no
//      branch); empty-ray fill is a rare separate branch.
//   2) fused raysum+scatter: one warp per ray, branch-uniform 2-deep load
//      loop, parity-preserving butterfly, per-ray sum write + broadcast
//      scatter (proven best shape, 32 regs / 8 blocks per SM).

#define MAX_RAYS_PAD (1 << 20)
__device__ int g_off[MAX_RAYS_PAD + 1];

// Guaranteed-predicated conditional store: avoids BSSY/BSYNC per element.
__device__ __forceinline__ void cond_store(int* addr, int a, int b, int val) {
    asm volatile(
        "{\n\t"
        ".reg .pred p;\n\t"
        "setp.ne.s32 p, %1, %2;\n\t"
        "@p st.global.s32 [%0], %3;\n\t"
        "}"
        :: "l"(addr), "r"(a), "r"(b), "r"(val)
        : "memory");
}

// ---------------- boundary kernel ----------------
#define BBLOCK 256
#define BRUN 16
#define B_SAMPLES (BBLOCK * BRUN)

__global__ void __launch_bounds__(BBLOCK)
boundary_kernel(const int* __restrict__ idx,
                int n_samples, int n_rays) {
    const int lane = threadIdx.x & 31;
    int base = (blockIdx.x * BBLOCK + threadIdx.x) * BRUN;
    const bool active = base < n_samples;
    const bool full = active && (base + BRUN <= n_samples);

    int r[BRUN];
    if (full) {
        const int4* p = reinterpret_cast<const int4*>(idx + base);
        #pragma unroll
        for (int q = 0; q < BRUN / 4; q++) {
            int4 v = p[q];
            r[q * 4 + 0] = v.x; r[q * 4 + 1] = v.y;
            r[q * 4 + 2] = v.z; r[q * 4 + 3] = v.w;
        }
    } else {
        #pragma unroll
        for (int s = 0; s < BRUN; s++) r[s] = 0;
    }

    // prev = preceding thread's last element via shuffle; only lane 0 does a
    // scalar global load.
    int prev = __shfl_up_sync(0xFFFFFFFFu, r[BRUN - 1], 1);
    if (lane == 0) prev = (base == 0) ? -1 : (active ? idx[base - 1] : 0);
    if (!active) return;

    if (full) {
        // Branch-free common path: one predicated store per element.
        #pragma unroll
        for (int s = 0; s < BRUN; s++) {
            int left = (s == 0) ? prev : r[s - 1];
            cond_store(g_off + r[s], r[s], left, base + s);
            // Empty-ray fill: P(empty) ~ e^-64, essentially never taken.
            if (r[s] > left + 1) {
                for (int q = left + 1; q < r[s]; q++) g_off[q] = base + s;
            }
        }
        if (base + BRUN == n_samples) {
            for (int q = r[BRUN - 1] + 1; q <= n_rays; q++) g_off[q] = n_samples;
        }
    } else {
        // Ragged tail: scalar path (at most one thread).
        int cnt = n_samples - base;
        int pv = prev;
        for (int s = 0; s < cnt; s++) {
            int rs = idx[base + s];
            if (rs != pv) {
                for (int q = pv + 1; q <= rs; q++) g_off[q] = base + s;
            }
            pv = rs;
        }
        if (base + cnt == n_samples) {
            for (int q = pv + 1; q <= n_rays; q++) g_off[q] = n_samples;
        }
    }
}

// ------- fused ray-sum + scatter kernel: one warp per ray -------
#define RSBLOCK 256
#define RAYS_PER_BLOCK (RSBLOCK / 32)

__global__ void __launch_bounds__(RSBLOCK, 8)
raysum_scatter_kernel(const float4* __restrict__ vals,  // 2 float4 per sample
                      float4* __restrict__ sums,        // 2 float4 per ray
                      float4* __restrict__ out,         // 2 float4 per sample
                      int n_rays) {
    int warp = threadIdx.x >> 5;
    int lane = threadIdx.x & 31;
    int ray = blockIdx.x * RAYS_PER_BLOCK + warp;
    if (ray >= n_rays) return;

    // 32-bit indices: n_samples*2 = 8.4M fits comfortably.
    int a2 = g_off[ray] * 2;          // even -> lane parity == f4 parity
    int b2 = g_off[ray + 1] * 2;

    float4 acc0 = make_float4(0.f, 0.f, 0.f, 0.f);
    float4 acc1 = acc0;

    int j = a2 + lane;
    // Branch-uniform 2-deep loop (mean pack = 128 f4 -> ~2 iters).
    for (; j + 32 < b2; j += 64) {
        float4 v0 = __ldcs(vals + j);
        float4 v1 = __ldcs(vals + j + 32);
        acc0.x += v0.x; acc0.y += v0.y; acc0.z += v0.z; acc0.w += v0.w;
        acc1.x += v1.x; acc1.y += v1.y; acc1.z += v1.z; acc1.w += v1.w;
    }
    if (j < b2) {
        float4 v = __ldcs(vals + j);
        acc0.x += v.x; acc0.y += v.y; acc0.z += v.z; acc0.w += v.w;
    }
    acc0.x += acc1.x; acc0.y += acc1.y; acc0.z += acc1.z; acc0.w += acc1.w;

    // Butterfly over even strides: every lane ends with the total for its
    // own parity (lane parity == float4-half parity).
    #pragma unroll
    for (int d = 2; d < 32; d <<= 1) {
        acc0.x += __shfl_xor_sync(0xFFFFFFFFu, acc0.x, d);
        acc0.y += __shfl_xor_sync(0xFFFFFFFFu, acc0.y, d);
        acc0.z += __shfl_xor_sync(0xFFFFFFFFu, acc0.z, d);
        acc0.w += __shfl_xor_sync(0xFFFFFFFFu, acc0.w, d);
    }

    // Per-ray sum: lane 0 holds half-0, lane 1 holds half-1.
    if (lane < 2) sums[ray * 2 + lane] = acc0;

    // Scatter the broadcast sum over the ray's contiguous output region.
    // out[j] parity == lane parity, so each lane stores its own acc0.
    j = a2 + lane;
    for (; j + 32 < b2; j += 64) {
        __stcs(out + j, acc0);
        __stcs(out + j + 32, acc0);
    }
    if (j < b2) __stcs(out + j, acc0);
}

extern "C" void kernel_launch(void* const* d_in, const int* in_sizes, int n_in,
                              void* d_out, int out_size) {
    const float4* vals = (const float4*)d_in[0];
    const int* idx = (const int*)d_in[1];

    int n_samples = in_sizes[1];                 // 4194304
    int n_rays = out_size / 8 - n_samples;       // 65536

    float4* sums = (float4*)d_out;                                    // [n_rays*2] float4
    float4* out_ps = (float4*)((float*)d_out + (size_t)n_rays * 8);   // [n_samples*2] float4

    // 1) ray pack offsets (one streaming pass over idx)
    {
        long long blocks = ((long long)n_samples + B_SAMPLES - 1) / B_SAMPLES;
        boundary_kernel<<<(unsigned)blocks, BBLOCK>>>(idx, n_samples, n_rays);
    }

    // 2) fused: one warp per ray -> sum + per-ray write + scatter write
    {
        long long blocks = ((long long)n_rays + RAYS_PER_BLOCK - 1) / RAYS_PER_BLOCK;
        raysum_scatter_kernel<<<(unsigned)blocks, RSBLOCK>>>(vals, sums, out_ps,
                                                             n_rays);
    }
}

// round 15
// speedup vs baseline: 1.0055x; 1.0055x over previous
#include <cuda_runtime.h>

// Segment-sum over sorted ray_indices + gather back — SINGLE kernel.
// Output: d_out[0 .. n_rays*8)                    = per-ray sums
//         d_out[n_rays*8 .. n_rays*8+n_samples*8) = per-sample gathered sums
//
// Sorted indices => each ray is a contiguous pack [a, b). One warp per ray:
// lanes 0/1 binary-search lower_bound(ray)/lower_bound(ray+1) concurrently
// (upper search-tree levels are L1/L2-hot; idx is fully L2-resident), then
// the warp streams the pack (2-deep branch-uniform loop), butterfly-reduces
// with parity preservation, writes the per-ray sum, and broadcasts the sum
// over the pack's contiguous output region. No scratch, no second launch.

#define RSBLOCK 256
#define RAYS_PER_BLOCK (RSBLOCK / 32)

__global__ void __launch_bounds__(RSBLOCK, 7)
raysum_scatter_kernel(const float4* __restrict__ vals,  // 2 float4 per sample
                      const int* __restrict__ idx,      // sorted ray ids
                      float4* __restrict__ sums,        // 2 float4 per ray
                      float4* __restrict__ out,         // 2 float4 per sample
                      int n_samples, int n_rays) {
    int warp = threadIdx.x >> 5;
    int lane = threadIdx.x & 31;
    int ray = blockIdx.x * RAYS_PER_BLOCK + warp;
    if (ray >= n_rays) return;

    // Lanes 0 and 1 search concurrently; other lanes ride along (no extra
    // latency). lower_bound: first i with idx[i] >= target.
    int target = ray + (lane & 1);
    int lo = 0, hi = n_samples;
    while (lo < hi) {
        int mid = (lo + hi) >> 1;
        if (__ldg(idx + mid) < target) lo = mid + 1;
        else hi = mid;
    }
    int a = __shfl_sync(0xFFFFFFFFu, lo, 0);
    int b = __shfl_sync(0xFFFFFFFFu, lo, 1);

    // 32-bit float4 indices: n_samples*2 = 8.4M fits comfortably.
    int a2 = a * 2;                   // even -> lane parity == f4 parity
    int b2 = b * 2;

    float4 acc0 = make_float4(0.f, 0.f, 0.f, 0.f);
    float4 acc1 = acc0;

    int j = a2 + lane;
    // Branch-uniform 2-deep loop (mean pack = 128 f4 -> ~2 iters).
    for (; j + 32 < b2; j += 64) {
        float4 v0 = __ldcs(vals + j);
        float4 v1 = __ldcs(vals + j + 32);
        acc0.x += v0.x; acc0.y += v0.y; acc0.z += v0.z; acc0.w += v0.w;
        acc1.x += v1.x; acc1.y += v1.y; acc1.z += v1.z; acc1.w += v1.w;
    }
    if (j < b2) {
        float4 v = __ldcs(vals + j);
        acc0.x += v.x; acc0.y += v.y; acc0.z += v.z; acc0.w += v.w;
    }
    acc0.x += acc1.x; acc0.y += acc1.y; acc0.z += acc1.z; acc0.w += acc1.w;

    // Butterfly over even strides: every lane ends with the total for its
    // own parity (lane parity == float4-half parity).
    #pragma unroll
    for (int d = 2; d < 32; d <<= 1) {
        acc0.x += __shfl_xor_sync(0xFFFFFFFFu, acc0.x, d);
        acc0.y += __shfl_xor_sync(0xFFFFFFFFu, acc0.y, d);
        acc0.z += __shfl_xor_sync(0xFFFFFFFFu, acc0.z, d);
        acc0.w += __shfl_xor_sync(0xFFFFFFFFu, acc0.w, d);
    }

    // Per-ray sum: lane 0 holds half-0, lane 1 holds half-1.
    // (Empty ray: a==b -> acc0 is zero, still written.)
    if (lane < 2) sums[ray * 2 + lane] = acc0;

    // Scatter the broadcast sum over the ray's contiguous output region.
    // out[j] parity == lane parity, so each lane stores its own acc0.
    j = a2 + lane;
    for (; j + 32 < b2; j += 64) {
        __stcs(out + j, acc0);
        __stcs(out + j + 32, acc0);
    }
    if (j < b2) __stcs(out + j, acc0);
}

extern "C" void kernel_launch(void* const* d_in, const int* in_sizes, int n_in,
                              void* d_out, int out_size) {
    const float4* vals = (const float4*)d_in[0];
    const int* idx = (const int*)d_in[1];

    int n_samples = in_sizes[1];                 // 4194304
    int n_rays = out_size / 8 - n_samples;       // 65536

    float4* sums = (float4*)d_out;                                    // [n_rays*2] float4
    float4* out_ps = (float4*)((float*)d_out + (size_t)n_rays * 8);   // [n_samples*2] float4

    long long blocks = ((long long)n_rays + RAYS_PER_BLOCK - 1) / RAYS_PER_BLOCK;
    raysum_scatter_kernel<<<(unsigned)blocks, RSBLOCK>>>(
        vals, idx, sums, out_ps, n_samples, n_rays);
}

// round 16
// speedup vs baseline: 1.1188x; 1.1127x over previous
#include <cuda_runtime.h>

// Segment-sum over sorted ray_indices + gather back.
// Output: d_out[0 .. n_rays*8)                    = per-ray sums
//         d_out[n_rays*8 .. n_rays*8+n_samples*8) = per-sample gathered sums
//
// Sorted indices => each ray is a contiguous pack.
//   1) boundary_kernel: streaming pass over idx -> pack offsets (static
//      __device__ scratch). Fast path: a 16-element run with
//      r[0]==r[15] (78% of threads) has at most one boundary (at its start).
//   2) fused raysum+scatter: one warp per ray, branch-uniform 2-deep load
//      loop, parity-preserving butterfly, per-ray sum write + broadcast
//      scatter (proven best shape: 32 regs, 8 blocks/SM).

#define MAX_RAYS_PAD (1 << 20)
__device__ int g_off[MAX_RAYS_PAD + 1];

// ---------------- boundary kernel ----------------
#define BBLOCK 256
#define BRUN 16
#define B_SAMPLES (BBLOCK * BRUN)

__global__ void __launch_bounds__(BBLOCK)
boundary_kernel(const int* __restrict__ idx,
                int n_samples, int n_rays) {
    const int lane = threadIdx.x & 31;
    int base = (blockIdx.x * BBLOCK + threadIdx.x) * BRUN;
    const bool active = base < n_samples;
    const bool full = active && (base + BRUN <= n_samples);

    int r[BRUN];
    if (full) {
        const int4* p = reinterpret_cast<const int4*>(idx + base);
        #pragma unroll
        for (int q = 0; q < BRUN / 4; q++) {
            int4 v = p[q];
            r[q * 4 + 0] = v.x; r[q * 4 + 1] = v.y;
            r[q * 4 + 2] = v.z; r[q * 4 + 3] = v.w;
        }
    } else {
        #pragma unroll
        for (int s = 0; s < BRUN; s++) r[s] = 0;
    }

    // prev = preceding thread's last element via shuffle; only lane 0 does a
    // scalar global load.
    int prev = __shfl_up_sync(0xFFFFFFFFu, r[BRUN - 1], 1);
    if (lane == 0) prev = (base == 0) ? -1 : (active ? idx[base - 1] : 0);
    if (!active) return;

    if (full) {
        if (r[0] == r[BRUN - 1]) {
            // Fast path (~78% of threads): whole run is one ray. The only
            // possible boundary is at the run start; the fill loop also
            // covers (rare) empty rays.
            if (r[0] != prev) {
                for (int q = prev + 1; q <= r[0]; q++) g_off[q] = base;
            }
        } else {
            // General path: walk the run.
            #pragma unroll
            for (int s = 0; s < BRUN; s++) {
                if (r[s] != prev) {
                    for (int q = prev + 1; q <= r[s]; q++) g_off[q] = base + s;
                }
                prev = r[s];
            }
        }
        if (base + BRUN == n_samples) {
            for (int q = r[BRUN - 1] + 1; q <= n_rays; q++) g_off[q] = n_samples;
        }
    } else {
        // Ragged tail: scalar path (at most one thread).
        int cnt = n_samples - base;
        int pv = prev;
        for (int s = 0; s < cnt; s++) {
            int rs = idx[base + s];
            if (rs != pv) {
                for (int q = pv + 1; q <= rs; q++) g_off[q] = base + s;
            }
            pv = rs;
        }
        for (int q = pv + 1; q <= n_rays; q++) g_off[q] = n_samples;
    }
}

// ------- fused ray-sum + scatter kernel: one warp per ray -------
#define RSBLOCK 256
#define RAYS_PER_BLOCK (RSBLOCK / 32)

__global__ void __launch_bounds__(RSBLOCK, 8)
raysum_scatter_kernel(const float4* __restrict__ vals,  // 2 float4 per sample
                      float4* __restrict__ sums,        // 2 float4 per ray
                      float4* __restrict__ out,         // 2 float4 per sample
                      int n_rays) {
    int warp = threadIdx.x >> 5;
    int lane = threadIdx.x & 31;
    int ray = blockIdx.x * RAYS_PER_BLOCK + warp;
    if (ray >= n_rays) return;

    // 32-bit indices: n_samples*2 = 8.4M fits comfortably.
    int a2 = g_off[ray] * 2;          // even -> lane parity == f4 parity
    int b2 = g_off[ray + 1] * 2;

    float4 acc0 = make_float4(0.f, 0.f, 0.f, 0.f);
    float4 acc1 = acc0;

    int j = a2 + lane;
    // Branch-uniform 2-deep loop (mean pack = 128 f4 -> ~2 iters).
    for (; j + 32 < b2; j += 64) {
        float4 v0 = __ldcs(vals + j);
        float4 v1 = __ldcs(vals + j + 32);
        acc0.x += v0.x; acc0.y += v0.y; acc0.z += v0.z; acc0.w += v0.w;
        acc1.x += v1.x; acc1.y += v1.y; acc1.z += v1.z; acc1.w += v1.w;
    }
    if (j < b2) {
        float4 v = __ldcs(vals + j);
        acc0.x += v.x; acc0.y += v.y; acc0.z += v.z; acc0.w += v.w;
    }
    acc0.x += acc1.x; acc0.y += acc1.y; acc0.z += acc1.z; acc0.w += acc1.w;

    // Butterfly over even strides: every lane ends with the total for its
    // own parity (lane parity == float4-half parity).
    #pragma unroll
    for (int d = 2; d < 32; d <<= 1) {
        acc0.x += __shfl_xor_sync(0xFFFFFFFFu, acc0.x, d);
        acc0.y += __shfl_xor_sync(0xFFFFFFFFu, acc0.y, d);
        acc0.z += __shfl_xor_sync(0xFFFFFFFFu, acc0.z, d);
        acc0.w += __shfl_xor_sync(0xFFFFFFFFu, acc0.w, d);
    }

    // Per-ray sum: lane 0 holds half-0, lane 1 holds half-1.
    if (lane < 2) sums[ray * 2 + lane] = acc0;

    // Scatter the broadcast sum over the ray's contiguous output region.
    // out[j] parity == lane parity, so each lane stores its own acc0.
    j = a2 + lane;
    for (; j + 32 < b2; j += 64) {
        __stcs(out + j, acc0);
        __stcs(out + j + 32, acc0);
    }
    if (j < b2) __stcs(out + j, acc0);
}

extern "C" void kernel_launch(void* const* d_in, const int* in_sizes, int n_in,
                              void* d_out, int out_size) {
    const float4* vals = (const float4*)d_in[0];
    const int* idx = (const int*)d_in[1];

    int n_samples = in_sizes[1];                 // 4194304
    int n_rays = out_size / 8 - n_samples;       // 65536

    float4* sums = (float4*)d_out;                                    // [n_rays*2] float4
    float4* out_ps = (float4*)((float*)d_out + (size_t)n_rays * 8);   // [n_samples*2] float4

    // 1) ray pack offsets (one streaming pass over idx)
    {
        long long blocks = ((long long)n_samples + B_SAMPLES - 1) / B_SAMPLES;
        boundary_kernel<<<(unsigned)blocks, BBLOCK>>>(idx, n_samples, n_rays);
    }

    // 2) fused: one warp per ray -> sum + per-ray write + scatter write
    {
        long long blocks = ((long long)n_rays + RAYS_PER_BLOCK - 1) / RAYS_PER_BLOCK;
        raysum_scatter_kernel<<<(unsigned)blocks, RSBLOCK>>>(vals, sums, out_ps,
                                                             n_rays);
    }
}

// round 17
// speedup vs baseline: 1.1647x; 1.0410x over previous
#include <cuda_runtime.h>

// Segment-sum over sorted ray_indices + gather back — ONE kernel, two roles.
// Output: d_out[0 .. n_rays*8)                    = per-ray sums
//         d_out[n_rays*8 .. n_rays*8+n_samples*8) = per-sample gathered sums
//
// Sorted indices => each ray is a contiguous pack.
//  Role A (blocks [0, NB_B)): boundary walk over idx -> g_off pack offsets.
//  Role B (blocks [NB_B, ...)): one warp per ray; spins until its g_off
//    entries leave the -1 sentinel (ld.global.cg + nanosleep), then streams
//    the pack, butterfly-reduces (parity-preserving), writes the per-ray
//    sum and broadcasts it over the pack's output region.
//  g_off is pre-poisoned to -1 by a memset node; each entry transitions
//  -1 -> value with one word store, so readers need no fences. Boundary
//  blocks have the lowest bids and never wait => no deadlock.

#define MAX_RAYS_PAD (1 << 20)
__device__ int g_off[MAX_RAYS_PAD + 1];

#define BBLOCK 256
#define BRUN 16
#define B_SAMPLES (BBLOCK * BRUN)

#define RAYS_PER_BLOCK 8   // 256 threads / 32

__device__ __forceinline__ int ld_cg(const int* p) {
    int v;
    asm volatile("ld.global.cg.s32 %0, [%1];" : "=r"(v) : "l"(p));
    return v;
}

__device__ __forceinline__ void boundary_role(const int* __restrict__ idx,
                                              int bbid, int n_samples,
                                              int n_rays) {
    const int lane = threadIdx.x & 31;
    int base = (bbid * BBLOCK + threadIdx.x) * BRUN;
    const bool active = base < n_samples;
    const bool full = active && (base + BRUN <= n_samples);

    int r[BRUN];
    if (full) {
        const int4* p = reinterpret_cast<const int4*>(idx + base);
        #pragma unroll
        for (int q = 0; q < BRUN / 4; q++) {
            int4 v = p[q];
            r[q * 4 + 0] = v.x; r[q * 4 + 1] = v.y;
            r[q * 4 + 2] = v.z; r[q * 4 + 3] = v.w;
        }
    } else {
        #pragma unroll
        for (int s = 0; s < BRUN; s++) r[s] = 0;
    }

    // prev = preceding thread's last element via shuffle; only lane 0 does a
    // scalar global load.
    int prev = __shfl_up_sync(0xFFFFFFFFu, r[BRUN - 1], 1);
    if (lane == 0) prev = (base == 0) ? -1 : (active ? idx[base - 1] : 0);
    if (!active) return;

    if (full) {
        #pragma unroll
        for (int s = 0; s < BRUN; s++) {
            if (r[s] != prev) {
                for (int q = prev + 1; q <= r[s]; q++) g_off[q] = base + s;
            }
            prev = r[s];
        }
        if (base + BRUN == n_samples) {
            for (int q = r[BRUN - 1] + 1; q <= n_rays; q++) g_off[q] = n_samples;
        }
    } else {
        // Ragged tail: scalar path (at most one thread).
        int cnt = n_samples - base;
        int pv = prev;
        for (int s = 0; s < cnt; s++) {
            int rs = idx[base + s];
            if (rs != pv) {
                for (int q = pv + 1; q <= rs; q++) g_off[q] = base + s;
            }
            pv = rs;
        }
        for (int q = pv + 1; q <= n_rays; q++) g_off[q] = n_samples;
    }
}

__device__ __forceinline__ void fused_role(const float4* __restrict__ vals,
                                           float4* __restrict__ sums,
                                           float4* __restrict__ out,
                                           int fbid, int n_rays) {
    int warp = threadIdx.x >> 5;
    int lane = threadIdx.x & 31;
    int ray = fbid * RAYS_PER_BLOCK + warp;
    if (ray >= n_rays) return;

    // Spin until both pack offsets are published (-1 sentinel cleared).
    // ld.global.cg bypasses L1 so updates are observed; nanosleep backoff.
    int a, b;
    while ((a = ld_cg(&g_off[ray])) == -1) { __nanosleep(64); }
    while ((b = ld_cg(&g_off[ray + 1])) == -1) { __nanosleep(64); }

    int a2 = a * 2;                   // even -> lane parity == f4 parity
    int b2 = b * 2;

    float4 acc0 = make_float4(0.f, 0.f, 0.f, 0.f);
    float4 acc1 = acc0;

    int j = a2 + lane;
    // Branch-uniform 2-deep loop (mean pack = 128 f4 -> ~2 iters).
    for (; j + 32 < b2; j += 64) {
        float4 v0 = __ldcs(vals + j);
        float4 v1 = __ldcs(vals + j + 32);
        acc0.x += v0.x; acc0.y += v0.y; acc0.z += v0.z; acc0.w += v0.w;
        acc1.x += v1.x; acc1.y += v1.y; acc1.z += v1.z; acc1.w += v1.w;
    }
    if (j < b2) {
        float4 v = __ldcs(vals + j);
        acc0.x += v.x; acc0.y += v.y; acc0.z += v.z; acc0.w += v.w;
    }
    acc0.x += acc1.x; acc0.y += acc1.y; acc0.z += acc1.z; acc0.w += acc1.w;

    // Butterfly over even strides: every lane ends with the total for its
    // own parity (lane parity == float4-half parity).
    #pragma unroll
    for (int d = 2; d < 32; d <<= 1) {
        acc0.x += __shfl_xor_sync(0xFFFFFFFFu, acc0.x, d);
        acc0.y += __shfl_xor_sync(0xFFFFFFFFu, acc0.y, d);
        acc0.z += __shfl_xor_sync(0xFFFFFFFFu, acc0.z, d);
        acc0.w += __shfl_xor_sync(0xFFFFFFFFu, acc0.w, d);
    }

    // Per-ray sum: lane 0 holds half-0, lane 1 holds half-1.
    if (lane < 2) sums[ray * 2 + lane] = acc0;

    // Scatter the broadcast sum over the ray's contiguous output region.
    // out[j] parity == lane parity, so each lane stores its own acc0.
    j = a2 + lane;
    for (; j + 32 < b2; j += 64) {
        __stcs(out + j, acc0);
        __stcs(out + j + 32, acc0);
    }
    if (j < b2) __stcs(out + j, acc0);
}

__global__ void __launch_bounds__(256, 7)
fused_all_kernel(const float4* __restrict__ vals,
                 const int* __restrict__ idx,
                 float4* __restrict__ sums,
                 float4* __restrict__ out,
                 int n_samples, int n_rays, int nb_boundary) {
    if ((int)blockIdx.x < nb_boundary) {
        boundary_role(idx, blockIdx.x, n_samples, n_rays);
    } else {
        fused_role(vals, sums, out, blockIdx.x - nb_boundary, n_rays);
    }
}

extern "C" void kernel_launch(void* const* d_in, const int* in_sizes, int n_in,
                              void* d_out, int out_size) {
    const float4* vals = (const float4*)d_in[0];
    const int* idx = (const int*)d_in[1];

    int n_samples = in_sizes[1];                 // 4194304
    int n_rays = out_size / 8 - n_samples;       // 65536

    float4* sums = (float4*)d_out;                                    // [n_rays*2] float4
    float4* out_ps = (float4*)((float*)d_out + (size_t)n_rays * 8);   // [n_samples*2] float4

    // Poison g_off entries [0, n_rays+1) to -1 (sentinel).
    static int* g_off_ptr = nullptr;
    if (!g_off_ptr) cudaGetSymbolAddress((void**)&g_off_ptr, g_off);
    cudaMemsetAsync(g_off_ptr, 0xFF, (size_t)(n_rays + 1) * sizeof(int));

    int nb_boundary = (n_samples + B_SAMPLES - 1) / B_SAMPLES;         // 1024 samples/blk
    int nb_fused = (n_rays + RAYS_PER_BLOCK - 1) / RAYS_PER_BLOCK;
    fused_all_kernel<<<(unsigned)(nb_boundary + nb_fused), 256>>>(
        vals, idx, sums, out_ps, n_samples, n_rays, nb_boundary);
}